// round 16
// baseline (speedup 1.0000x reference)
#include <cuda_runtime.h>
#include <cstdint>

// GaussianTrans via mma.sync tf32 (arch-agnostic PTX; tcgen05 is 'a'-gated).
//   outX[b,r,c,d] = sum_h sig(disX+attX) * V[b,r,h,d]   (X: write)
//   outY[b,r,c,d] = sum_w sig(disY+attY) * V[b,w,c,d]   (Y: accumulate)
// B=16, H=W=64, D=512.
// R14 (64m x 64n x 64k CTA, 8 warps of 16m x 32n, 4 CTAs/SM, fused 5-launch
// X(g)+Y(g-1) schedule) with ONE change: the epilogue stages accumulators
// through smem (reusing the A-tile region) and writes out with the same flat
// row-major mapping as the fills -> dense 128B-line LDG.128/STG.128 instead
// of 8-row-scattered STG.64/LDG.64 (which cost ~8 sparse sectors per inst).

#define SK 68    // As row stride (pad 4): conflict-free frag loads
#define SN 72    // Vs row stride (pad 8): conflict-free frag loads

static constexpr uint32_t SMEM_BYTES = (64 * SK + 64 * SN) * 4;  // 35840

static __device__ __forceinline__ uint32_t tf32rn(float f) {
    uint32_t r;
    asm("cvt.rn.tf32.f32 %0, %1;" : "=r"(r) : "f"(f));
    return r;
}
static __device__ __forceinline__ float fast_sigmoid(float t) {
    return __fdividef(1.0f, 1.0f + __expf(-t));
}
static __device__ __forceinline__ void mma_tf32(float& c0, float& c1, float& c2,
                                                float& c3, uint32_t a0, uint32_t a1,
                                                uint32_t a2, uint32_t a3,
                                                uint32_t b0, uint32_t b1) {
    asm volatile(
        "mma.sync.aligned.m16n8k8.row.col.f32.tf32.tf32.f32 "
        "{%0,%1,%2,%3}, {%4,%5,%6,%7}, {%8,%9}, {%0,%1,%2,%3};"
        : "+f"(c0), "+f"(c1), "+f"(c2), "+f"(c3)
        : "r"(a0), "r"(a1), "r"(a2), "r"(a3), "r"(b0), "r"(b1));
}

__global__ __launch_bounds__(256, 4)
void gt_mma(const float* __restrict__ attX, const float* __restrict__ attY,
            const float* __restrict__ V, float* __restrict__ out,
            const float* __restrict__ shift, const float* __restrict__ bias,
            int bx0, int by0, int nx)
{
    extern __shared__ float smem[];
    float* As = smem;             // [64][SK], tf32-RN bit patterns
    float* Vs = smem + 64 * SK;   // [64][SN], raw fp32 (HW truncates to tf32)

    const int tid = threadIdx.x;
    const int dt    = blockIdx.x;          // 0..7 (d tile of 64)
    const int outer = blockIdx.y;          // r (pass X) or c (pass Y)
    const int z     = blockIdx.z;
    const bool passY = (z >= nx);
    const int b      = passY ? (by0 + z - nx) : (bx0 + z);
    const float* att = passY ? attY : attX;

    const float sh = shift[0], bi = bias[0];
    const int attBase = (b * 64 + outer) * 4096;
    const int off     = passY ? (b * 2097152 + outer * 512)
                              : ((b * 64 + outer) * 32768);
    const int vstride = passY ? 32768 : 512;
    const int dbase   = dt * 64;

    // --- A tile: sigmoid(dis + att) -> tf32-RN; coalesced float4 in ---
    #pragma unroll
    for (int j = 0; j < 4; ++j) {
        const int idx4 = tid + j * 256;          // 1024 float4 = 4096 elems
        const int m  = idx4 >> 4;
        const int k4 = (idx4 & 15) << 2;
        const float4 av = *reinterpret_cast<const float4*>(att + attBase + idx4 * 4);
        float d0 = (float)(k4 + 0 - m);
        float d1 = (float)(k4 + 1 - m);
        float d2 = (float)(k4 + 2 - m);
        float d3 = (float)(k4 + 3 - m);
        uint4 sv;
        sv.x = tf32rn(fast_sigmoid(fmaf(-sh * d0, d0, av.x - bi)));
        sv.y = tf32rn(fast_sigmoid(fmaf(-sh * d1, d1, av.y - bi)));
        sv.z = tf32rn(fast_sigmoid(fmaf(-sh * d2, d2, av.z - bi)));
        sv.w = tf32rn(fast_sigmoid(fmaf(-sh * d3, d3, av.w - bi)));
        *reinterpret_cast<uint4*>(&As[m * SK + k4]) = sv;
    }

    // --- V tile: 64 k-rows x 64 d, raw fp32 bits ---
    #pragma unroll
    for (int j = 0; j < 4; ++j) {
        const int idx4 = tid + j * 256;          // 1024 float4
        const int row  = idx4 >> 4;
        const int col  = (idx4 & 15) << 2;
        const float4 vv = *reinterpret_cast<const float4*>(
            V + off + row * vstride + dbase + col);
        *reinterpret_cast<float4*>(&Vs[row * SN + col]) = vv;
    }
    __syncthreads();

    // --- mma.sync m16n8k8 tf32: warp = 16m x 32n (4 n-tiles, 16 accs) ---
    const int wid  = tid >> 5;      // 0..7
    const int lane = tid & 31;
    const int grp  = lane >> 2;     // 0..7
    const int tig  = lane & 3;      // 0..3
    const int mrow = (wid & 3) * 16;
    const int n0   = (wid >> 2) * 32;

    float acc[4][4];
    #pragma unroll
    for (int nt = 0; nt < 4; ++nt)
        #pragma unroll
        for (int q = 0; q < 4; ++q) acc[nt][q] = 0.0f;

    const uint32_t* Au = reinterpret_cast<const uint32_t*>(As);
    const uint32_t* Vu = reinterpret_cast<const uint32_t*>(Vs);

    #pragma unroll
    for (int k8 = 0; k8 < 8; ++k8) {
        const int kb = k8 * 8;
        const int base = (mrow + grp) * SK + kb + tig;
        const uint32_t a0 = Au[base];               // (row,   col)
        const uint32_t a1 = Au[base + 8 * SK];      // (row+8, col)
        const uint32_t a2 = Au[base + 4];           // (row,   col+4)
        const uint32_t a3 = Au[base + 8 * SK + 4];  // (row+8, col+4)
        #pragma unroll
        for (int nt = 0; nt < 4; ++nt) {
            const int nc = n0 + nt * 8 + grp;
            const uint32_t bq0 = Vu[(kb + tig) * SN + nc];
            const uint32_t bq1 = Vu[(kb + tig + 4) * SN + nc];
            mma_tf32(acc[nt][0], acc[nt][1], acc[nt][2], acc[nt][3],
                     a0, a1, a2, a3, bq0, bq1);
        }
    }

    // --- epilogue: stage through smem (reuse A region), then dense 128B I/O ---
    __syncthreads();                      // k-loop done reading As
    float* Os = smem;                     // [64][SK] staging (64x68 fits A area)
    #pragma unroll
    for (int nt = 0; nt < 4; ++nt) {
        const int col = n0 + nt * 8 + tig * 2;     // local d 0..63
        const int r0  = mrow + grp;
        *reinterpret_cast<float2*>(&Os[r0 * SK + col]) =
            make_float2(acc[nt][0], acc[nt][1]);
        *reinterpret_cast<float2*>(&Os[(r0 + 8) * SK + col]) =
            make_float2(acc[nt][2], acc[nt][3]);
    }
    __syncthreads();

    #pragma unroll
    for (int j = 0; j < 4; ++j) {
        const int idx4 = tid + j * 256;            // 1024 float4 = 64 rows x 16
        const int row  = idx4 >> 4;
        const int col  = (idx4 & 15) << 2;
        float4 w = *reinterpret_cast<const float4*>(&Os[row * SK + col]);
        float* p = out + off + row * vstride + dbase + col;
        if (passY) {
            const float4 o = *reinterpret_cast<const float4*>(p);
            w.x += o.x; w.y += o.y; w.z += o.z; w.w += o.w;
        }
        *reinterpret_cast<float4*>(p) = w;
    }
}

extern "C" void kernel_launch(void* const* d_in, const int* in_sizes, int n_in,
                              void* d_out, int out_size) {
    (void)in_sizes; (void)n_in; (void)out_size;
    // metadata order: x(unused), attentionXFull, attentionYFull, valueFull, shift, bias
    const float* attX  = (const float*)d_in[1];
    const float* attY  = (const float*)d_in[2];
    const float* V     = (const float*)d_in[3];
    const float* shift = (const float*)d_in[4];
    const float* bias  = (const float*)d_in[5];
    float* out = (float*)d_out;

    cudaFuncSetAttribute(gt_mma, cudaFuncAttributeMaxDynamicSharedMemorySize,
                         SMEM_BYTES);

    dim3 block(256);
    // Pipelined schedule: launch i = X(group i) + Y(group i-1); 5 launches.
    // Y(b) reads outX(b) written by the PREVIOUS launch (stream-ordered).
    gt_mma<<<dim3(8, 64, 4), block, SMEM_BYTES>>>(attX, attY, V, out, shift, bias,
                                                  0, 0, 4);
    for (int g = 1; g < 4; ++g)
        gt_mma<<<dim3(8, 64, 8), block, SMEM_BYTES>>>(attX, attY, V, out, shift,
                                                      bias, g * 4, (g - 1) * 4, 4);
    gt_mma<<<dim3(8, 64, 4), block, SMEM_BYTES>>>(attX, attY, V, out, shift, bias,
                                                  0, 12, 0);
}

// round 17
// speedup vs baseline: 1.0689x; 1.0689x over previous
#include <cuda_runtime.h>
#include <cstdint>

// GaussianTrans via mma.sync tf32 (arch-agnostic PTX; tcgen05 is 'a'-gated).
//   outX[b,r,c,d] = sum_h sig(disX+attX) * V[b,r,h,d]   (X: write)
//   outY[b,r,c,d] = sum_w sig(disY+attY) * V[b,w,c,d]   (Y: accumulate)
// B=16, H=W=64, D=512.
// R14 base (64m x 64n x 64k CTA, 8 warps of 16m x 32n, 4 CTAs/SM, fused
// 5-launch X(g)+Y(g-1) schedule, scattered direct epilogue) with ONE change:
// A fragments loaded via ldmatrix.m8n8.x4 (1 LDSM instead of 4 scalar LDS
// per k8 per warp) -> k-loop L1 instructions drop 96 -> 72 per warp-tile.

#define SK 68    // As row stride (pad 4): LDSM rows hit banks {0,4,..,28}
#define SN 72    // Vs row stride (pad 8): conflict-free frag loads

static constexpr uint32_t SMEM_BYTES = (64 * SK + 64 * SN) * 4;  // 35840

static __device__ __forceinline__ uint32_t tf32rn(float f) {
    uint32_t r;
    asm("cvt.rn.tf32.f32 %0, %1;" : "=r"(r) : "f"(f));
    return r;
}
static __device__ __forceinline__ float fast_sigmoid(float t) {
    return __fdividef(1.0f, 1.0f + __expf(-t));
}
static __device__ __forceinline__ uint32_t smem_u32(const void* p) {
    uint32_t a;
    asm("{ .reg .u64 t; cvta.to.shared.u64 t, %1; cvt.u32.u64 %0, t; }"
        : "=r"(a) : "l"(p));
    return a;
}
static __device__ __forceinline__ void mma_tf32(float& c0, float& c1, float& c2,
                                                float& c3, uint32_t a0, uint32_t a1,
                                                uint32_t a2, uint32_t a3,
                                                uint32_t b0, uint32_t b1) {
    asm volatile(
        "mma.sync.aligned.m16n8k8.row.col.f32.tf32.tf32.f32 "
        "{%0,%1,%2,%3}, {%4,%5,%6,%7}, {%8,%9}, {%0,%1,%2,%3};"
        : "+f"(c0), "+f"(c1), "+f"(c2), "+f"(c3)
        : "r"(a0), "r"(a1), "r"(a2), "r"(a3), "r"(b0), "r"(b1));
}

__global__ __launch_bounds__(256, 4)
void gt_mma(const float* __restrict__ attX, const float* __restrict__ attY,
            const float* __restrict__ V, float* __restrict__ out,
            const float* __restrict__ shift, const float* __restrict__ bias,
            int bx0, int by0, int nx)
{
    extern __shared__ float smem[];
    float* As = smem;             // [64][SK], tf32-RN bit patterns
    float* Vs = smem + 64 * SK;   // [64][SN], raw fp32 (HW truncates to tf32)

    const int tid = threadIdx.x;
    const int dt    = blockIdx.x;          // 0..7 (d tile of 64)
    const int outer = blockIdx.y;          // r (pass X) or c (pass Y)
    const int z     = blockIdx.z;
    const bool passY = (z >= nx);
    const int b      = passY ? (by0 + z - nx) : (bx0 + z);
    const float* att = passY ? attY : attX;

    const float sh = shift[0], bi = bias[0];
    const int attBase = (b * 64 + outer) * 4096;
    const int off     = passY ? (b * 2097152 + outer * 512)
                              : ((b * 64 + outer) * 32768);
    const int vstride = passY ? 32768 : 512;
    const int dbase   = dt * 64;

    // --- A tile: sigmoid(dis + att) -> tf32-RN; coalesced float4 in ---
    #pragma unroll
    for (int j = 0; j < 4; ++j) {
        const int idx4 = tid + j * 256;          // 1024 float4 = 4096 elems
        const int m  = idx4 >> 4;
        const int k4 = (idx4 & 15) << 2;
        const float4 av = *reinterpret_cast<const float4*>(att + attBase + idx4 * 4);
        float d0 = (float)(k4 + 0 - m);
        float d1 = (float)(k4 + 1 - m);
        float d2 = (float)(k4 + 2 - m);
        float d3 = (float)(k4 + 3 - m);
        uint4 sv;
        sv.x = tf32rn(fast_sigmoid(fmaf(-sh * d0, d0, av.x - bi)));
        sv.y = tf32rn(fast_sigmoid(fmaf(-sh * d1, d1, av.y - bi)));
        sv.z = tf32rn(fast_sigmoid(fmaf(-sh * d2, d2, av.z - bi)));
        sv.w = tf32rn(fast_sigmoid(fmaf(-sh * d3, d3, av.w - bi)));
        *reinterpret_cast<uint4*>(&As[m * SK + k4]) = sv;
    }

    // --- V tile: 64 k-rows x 64 d, raw fp32 bits ---
    #pragma unroll
    for (int j = 0; j < 4; ++j) {
        const int idx4 = tid + j * 256;          // 1024 float4
        const int row  = idx4 >> 4;
        const int col  = (idx4 & 15) << 2;
        const float4 vv = *reinterpret_cast<const float4*>(
            V + off + row * vstride + dbase + col);
        *reinterpret_cast<float4*>(&Vs[row * SN + col]) = vv;
    }
    __syncthreads();

    // --- mma.sync m16n8k8 tf32: warp = 16m x 32n (4 n-tiles, 16 accs) ---
    const int wid  = tid >> 5;      // 0..7
    const int lane = tid & 31;
    const int grp  = lane >> 2;     // 0..7
    const int tig  = lane & 3;      // 0..3
    const int mrow = (wid & 3) * 16;
    const int n0   = (wid >> 2) * 32;

    float acc[4][4];
    #pragma unroll
    for (int nt = 0; nt < 4; ++nt)
        #pragma unroll
        for (int q = 0; q < 4; ++q) acc[nt][q] = 0.0f;

    const uint32_t* Vu = reinterpret_cast<const uint32_t*>(Vs);

    // ldmatrix lane address: mat = lane>>3; row = mrow + (lane&7) + (mat&1)*8;
    // col = (mat>>1)*4  (+ kb per iteration). Matches a0..a3 of m16k8 tf32.
    const uint32_t asb = smem_u32(As);
    const uint32_t aAddr0 = asb +
        4u * (uint32_t)((mrow + (lane & 7) + ((lane >> 3) & 1) * 8) * SK
                        + ((lane >> 4) << 2));

    #pragma unroll
    for (int k8 = 0; k8 < 8; ++k8) {
        const int kb = k8 * 8;
        uint32_t a0, a1, a2, a3;
        asm volatile(
            "ldmatrix.sync.aligned.m8n8.x4.shared.b16 {%0,%1,%2,%3}, [%4];"
            : "=r"(a0), "=r"(a1), "=r"(a2), "=r"(a3)
            : "r"(aAddr0 + (uint32_t)kb * 4u));
        #pragma unroll
        for (int nt = 0; nt < 4; ++nt) {
            const int nc = n0 + nt * 8 + grp;
            const uint32_t bq0 = Vu[(kb + tig) * SN + nc];
            const uint32_t bq1 = Vu[(kb + tig + 4) * SN + nc];
            mma_tf32(acc[nt][0], acc[nt][1], acc[nt][2], acc[nt][3],
                     a0, a1, a2, a3, bq0, bq1);
        }
    }

    // --- epilogue (R14 direct form): X writes; Y accumulates ---
    #pragma unroll
    for (int nt = 0; nt < 4; ++nt) {
        const int col  = dbase + n0 + nt * 8 + tig * 2;
        const int row0 = mrow + grp;
        float* p0 = out + off + row0 * vstride + col;
        float* p1 = p0 + 8 * vstride;
        float2 w0 = make_float2(acc[nt][0], acc[nt][1]);
        float2 w1 = make_float2(acc[nt][2], acc[nt][3]);
        if (passY) {
            const float2 o0 = *reinterpret_cast<const float2*>(p0);
            const float2 o1 = *reinterpret_cast<const float2*>(p1);
            w0.x += o0.x; w0.y += o0.y;
            w1.x += o1.x; w1.y += o1.y;
        }
        *reinterpret_cast<float2*>(p0) = w0;
        *reinterpret_cast<float2*>(p1) = w1;
    }
}

extern "C" void kernel_launch(void* const* d_in, const int* in_sizes, int n_in,
                              void* d_out, int out_size) {
    (void)in_sizes; (void)n_in; (void)out_size;
    // metadata order: x(unused), attentionXFull, attentionYFull, valueFull, shift, bias
    const float* attX  = (const float*)d_in[1];
    const float* attY  = (const float*)d_in[2];
    const float* V     = (const float*)d_in[3];
    const float* shift = (const float*)d_in[4];
    const float* bias  = (const float*)d_in[5];
    float* out = (float*)d_out;

    cudaFuncSetAttribute(gt_mma, cudaFuncAttributeMaxDynamicSharedMemorySize,
                         SMEM_BYTES);

    dim3 block(256);
    // Pipelined schedule: launch i = X(group i) + Y(group i-1); 5 launches.
    // Y(b) reads outX(b) written by the PREVIOUS launch (stream-ordered).
    gt_mma<<<dim3(8, 64, 4), block, SMEM_BYTES>>>(attX, attY, V, out, shift, bias,
                                                  0, 0, 4);
    for (int g = 1; g < 4; ++g)
        gt_mma<<<dim3(8, 64, 8), block, SMEM_BYTES>>>(attX, attY, V, out, shift,
                                                      bias, g * 4, (g - 1) * 4, 4);
    gt_mma<<<dim3(8, 64, 4), block, SMEM_BYTES>>>(attX, attY, V, out, shift, bias,
                                                  0, 12, 0);
}